// round 11
// baseline (speedup 1.0000x reference)
#include <cuda_runtime.h>
#include <cuda_fp16.h>
#include <cstdint>
#include <cstddef>
#include <math.h>

// ---------------------------------------------------------------------------
// GLN_56006373539841: HMMA fp16 GEMM, single-pass.
// R11: fp64 rescue FUSED into ctx-GEMM epilogue via smem work queue
//      (kills 3 latency-bound rescue launches, ~0.45 ms).
//   ctx GEMMs: fp16 + tau=0.08 fp64 rescue of near-threshold sign decisions
//   select GEMMs: single-pass fp16 (R10 config, 3-stage, 2 CTA/SM)
//   B=4096, D_IN=1024, D_LAT=2048, D_OUT=1024, SHATTER=3, NC=8
// ---------------------------------------------------------------------------

#define RESCUE_TAU 0.08f
#define PITCH   80                    // 64B data + 16B pad (KC=32 fp16 rows)

// select GEMM (NT=128): 2 tiles (A, B), 3 stages -> 2 CTAs/SM
#define SSTAGES 3
#define S_TILE  (128 * PITCH)         // 10240
#define S_STAGE (2 * S_TILE)          // 20480
#define S_SMEM  (SSTAGES * S_STAGE)   // 61440

// ctx GEMM (NT=192): 2 tiles (A, B), 4 stages (1 CTA/SM, reg-heavy)
#define CSTAGES 4
#define C_AB    (128 * PITCH)         // 10240
#define C_BB    (192 * PITCH)         // 15360
#define C_STAGE (C_AB + C_BB)         // 25600
#define C_SMEM  (CSTAGES * C_STAGE)   // 102400
#define SC_PITCH 194                  // score staging pitch (floats)
#define RQ_CAP  1024                  // rescue queue capacity (mean ~49/CTA)

// ============================ PTX helpers ==================================
__device__ __forceinline__ uint32_t smem_u32(const void* p) {
    uint32_t a;
    asm("{ .reg .u64 t; cvta.to.shared.u64 t, %1; cvt.u32.u64 %0, t; }"
        : "=r"(a) : "l"(p));
    return a;
}
__device__ __forceinline__ void cp16(uint32_t dst, const void* src) {
    asm volatile("cp.async.cg.shared.global [%0], [%1], 16;" :: "r"(dst), "l"(src));
}
#define CP_COMMIT() asm volatile("cp.async.commit_group;" ::: "memory")

__device__ __forceinline__ void ldsm4(uint32_t* r, uint32_t addr) {
    asm volatile("ldmatrix.sync.aligned.m8n8.x4.shared.b16 {%0,%1,%2,%3}, [%4];"
        : "=r"(r[0]), "=r"(r[1]), "=r"(r[2]), "=r"(r[3]) : "r"(addr));
}
__device__ __forceinline__ void hmma(float* d, const uint32_t* a, const uint32_t* b) {
    asm volatile("mma.sync.aligned.m16n8k16.row.col.f32.f16.f16.f32 "
        "{%0,%1,%2,%3},{%4,%5,%6,%7},{%8,%9},{%0,%1,%2,%3};"
        : "+f"(d[0]), "+f"(d[1]), "+f"(d[2]), "+f"(d[3])
        : "r"(a[0]), "r"(a[1]), "r"(a[2]), "r"(a[3]), "r"(b[0]), "r"(b[1]));
}

// ============================ scratch ======================================
__device__ __half g_xh [4096u * 1024u];
__device__ __half g_hA [4096u * 2048u];
__device__ __half g_hB [4096u * 2048u];
__device__ __half g_whA[6144u * 1024u];     // H conversions (contexts)
__device__ __half g_whB[16384u * 2048u];    // W conversions (largest: W1)
__device__ unsigned char g_ctx0[4096u * 2048u];
__device__ unsigned char g_ctx1[4096u * 2048u];
__device__ unsigned char g_ctx2[4096u * 1024u];

// ============================ convert kernel ===============================
__global__ void conv_hi(const float* __restrict__ in, __half* __restrict__ hi, int n4)
{
    int i = blockIdx.x * blockDim.x + threadIdx.x;
    if (i >= n4) return;
    float4 v = ((const float4*)in)[i];
    ((__half2*)hi)[i * 2 + 0] = __halves2half2(__float2half_rn(v.x), __float2half_rn(v.y));
    ((__half2*)hi)[i * 2 + 1] = __halves2half2(__float2half_rn(v.z), __float2half_rn(v.w));
}

// ============================ ctx GEMM (fused combine + rescue) ============
// CTA 128M x 192N, 8 warps (4M x 2N), warp tile 32x96.
// Epilogue: combine scores -> ctx bytes; flagged (|score-T|<tau) entries go
// to a smem queue and are re-decided in fp64 (warp-cooperative) in-kernel.
__global__ __launch_bounds__(256, 1)
void gemm_ctx(const __half* __restrict__ Ahi, const __half* __restrict__ Bhi,
              int K, int O,
              unsigned char* __restrict__ ctxout, const float* __restrict__ T,
              const float* __restrict__ zf, const float* __restrict__ Hf)
{
    extern __shared__ char smraw[];
    __shared__ uint32_t rq[RQ_CAP];
    __shared__ int rq_cnt;
    const uint32_t smb = smem_u32(smraw);
    const int tid  = threadIdx.x;
    const int lane = tid & 31;
    const int wid  = tid >> 5;
    const int wm   = wid & 3;
    const int wn   = wid >> 2;
    const int row0 = blockIdx.x * 128;
    const int col0 = blockIdx.y * 192;

    const __half* gA = Ahi + (size_t)row0 * K;
    const __half* gB = Bhi + (size_t)col0 * K;

    if (tid == 0) rq_cnt = 0;

    float acc[2][12][4];
#pragma unroll
    for (int i = 0; i < 2; i++)
#pragma unroll
        for (int j = 0; j < 12; j++)
#pragma unroll
            for (int q = 0; q < 4; q++) acc[i][j][q] = 0.0f;

    const int nk = K >> 5;

    auto issue = [&](int s) {
        uint32_t base = smb + (uint32_t)(s & (CSTAGES - 1)) * C_STAGE;
        int k0 = s * 32;
#pragma unroll
        for (int t = 0; t < 2; t++) {           // A: 512 cp16
            int id = tid + t * 256;
            int r  = id >> 2, c = id & 3;
            cp16(base + r * PITCH + c * 16, gA + (size_t)r * K + k0 + c * 8);
        }
#pragma unroll
        for (int t = 0; t < 3; t++) {           // B: 768 cp16
            int id = tid + t * 256;
            int r  = id >> 2, c = id & 3;
            cp16(base + C_AB + r * PITCH + c * 16, gB + (size_t)r * K + k0 + c * 8);
        }
        CP_COMMIT();
    };

#pragma unroll
    for (int s = 0; s < CSTAGES - 1; s++) issue(s);

    const uint32_t lrow = (uint32_t)(lane & 15);
    const uint32_t lhal = (uint32_t)(lane >> 4) * 16;

    for (int it = 0; it < nk; it++) {
        asm volatile("cp.async.wait_group 2;" ::: "memory");
        __syncthreads();
        int pf = it + CSTAGES - 1;
        if (pf < nk) issue(pf); else CP_COMMIT();

        uint32_t stg = smb + (uint32_t)(it & (CSTAGES - 1)) * C_STAGE;
#pragma unroll
        for (int k16 = 0; k16 < 2; k16++) {
            uint32_t koff = lhal + (uint32_t)k16 * 32;
            uint32_t ah[2][4];
#pragma unroll
            for (int mi = 0; mi < 2; mi++) {
                uint32_t ro = (uint32_t)(wm * 32 + mi * 16) + lrow;
                ldsm4(ah[mi], stg + ro * PITCH + koff);
            }
            uint32_t bh[12][2];
#pragma unroll
            for (int jj = 0; jj < 6; jj++) {
                uint32_t ro = (uint32_t)(wn * 96 + jj * 16) + lrow;
                uint32_t r4[4];
                ldsm4(r4, stg + C_AB + ro * PITCH + koff);
                bh[jj * 2][0] = r4[0]; bh[jj * 2][1] = r4[2];
                bh[jj * 2 + 1][0] = r4[1]; bh[jj * 2 + 1][1] = r4[3];
            }
#pragma unroll
            for (int mi = 0; mi < 2; mi++)
#pragma unroll
                for (int nj = 0; nj < 12; nj++) hmma(acc[mi][nj], ah[mi], bh[nj]);
        }
    }
    asm volatile("cp.async.wait_group 0;" ::: "memory");
    __syncthreads();

    // ---- stage scores into smem ----
    float* ssc = (float*)smraw;
    const int rr = lane >> 2;
    const int q2 = (lane & 3) * 2;
#pragma unroll
    for (int mi = 0; mi < 2; mi++) {
        int r_lo = wm * 32 + mi * 16 + rr;
        int r_hi = r_lo + 8;
#pragma unroll
        for (int nj = 0; nj < 12; nj++) {
            int c = wn * 96 + nj * 8 + q2;
            *(float2*)&ssc[r_lo * SC_PITCH + c] = make_float2(acc[mi][nj][0], acc[mi][nj][1]);
            *(float2*)&ssc[r_hi * SC_PITCH + c] = make_float2(acc[mi][nj][2], acc[mi][nj][3]);
        }
    }
    __syncthreads();

    // ---- combine: 128 rows x 64 o-groups; queue flagged entries ----
    const int oc0 = col0 / 3;
#pragma unroll
    for (int w8 = 0; w8 < 8; w8++) {
        int word_id = tid + w8 * 256;
        int r  = word_id >> 4;
        int wo = word_id & 15;
        const float* sp = ssc + r * SC_PITCH + wo * 12;
        uint32_t word = 0;
#pragma unroll
        for (int j = 0; j < 4; j++) {
            int ol = wo * 4 + j;             // o local (0..63)
            int o  = oc0 + ol;
            int c = 0, fm = 0;
#pragma unroll
            for (int s = 0; s < 3; s++) {
                float th = __ldg(T + o * 3 + s);
                float d  = sp[j * 3 + s] - th;
                c  |= ((int)(d > 0.0f)) << s;
                fm |= ((int)(fabsf(d) < RESCUE_TAU)) << s;
            }
            if (fm) {
                int slot = atomicAdd(&rq_cnt, 1);
                if (slot < RQ_CAP)
                    rq[slot] = (uint32_t)r | ((uint32_t)ol << 7) |
                               ((uint32_t)c << 13) | ((uint32_t)fm << 16);
            }
            word |= (uint32_t)((unsigned char)c) << (j * 8);
        }
        *(uint32_t*)(ctxout + (size_t)(row0 + r) * O + oc0 + wo * 4) = word;
    }
    __syncthreads();

    // ---- in-kernel fp64 rescue: warps drain the queue cooperatively ----
    int cnt = rq_cnt; if (cnt > RQ_CAP) cnt = RQ_CAP;
    for (int q = wid; q < cnt; q += 8) {
        uint32_t e = rq[q];
        int r  = (int)(e & 127u);
        int ol = (int)((e >> 7) & 63u);
        int c  = (int)((e >> 13) & 7u);
        int fm = (int)((e >> 16) & 7u);
        int gb = row0 + r;
        int go = oc0 + ol;
        const float* zr = zf + (size_t)gb * K;
#pragma unroll
        for (int s = 0; s < 3; s++) {
            if (!(fm & (1 << s))) continue;
            const float* hr = Hf + (size_t)(go * 3 + s) * K;
            double p0 = 0.0, p1 = 0.0;
            for (int k = lane; k < K; k += 64) {
                p0 += (double)zr[k]      * (double)hr[k];
                p1 += (double)zr[k + 32] * (double)hr[k + 32];
            }
            double part = p0 + p1;
#pragma unroll
            for (int off = 16; off; off >>= 1)
                part += __shfl_down_sync(0xFFFFFFFFu, part, off);
            part = __shfl_sync(0xFFFFFFFFu, part, 0);
            c = (c & ~(1 << s)) | (((int)(part > (double)__ldg(T + go * 3 + s))) << s);
        }
        if (lane == 0) ctxout[(size_t)gb * O + go] = (unsigned char)c;
    }
}

// ============================ select GEMM ==================================
// CTA 128x128, 8 warps (4M x 2N), warp tile 32x64.  3-stage smem + 2 CTAs/SM.
// MODE 1: hidden -> fp16.  MODE 2: final -> fp32.
template <int MODE>
__global__ __launch_bounds__(256, 2)
void gemm_sel(const __half* __restrict__ Ahi, const __half* __restrict__ Bhi,
              int K, int O,
              const unsigned char* __restrict__ ctx, const float* __restrict__ bias,
              float* __restrict__ outf, __half* __restrict__ outh)
{
    extern __shared__ char smraw[];
    const uint32_t smb = smem_u32(smraw);
    const int tid  = threadIdx.x;
    const int lane = tid & 31;
    const int wid  = tid >> 5;
    const int wm   = wid & 3;
    const int wn   = wid >> 2;
    const int row0 = blockIdx.x * 128;
    const int col0 = blockIdx.y * 128;

    const __half* gA = Ahi + (size_t)row0 * K;
    const __half* gB = Bhi + (size_t)col0 * K;

    float acc[2][8][4];
#pragma unroll
    for (int i = 0; i < 2; i++)
#pragma unroll
        for (int j = 0; j < 8; j++)
#pragma unroll
            for (int q = 0; q < 4; q++) acc[i][j][q] = 0.0f;

    const int nk = K >> 5;

    auto issue = [&](int s) {
        uint32_t base = smb + (uint32_t)((unsigned)s % 3u) * S_STAGE;
        int k0 = s * 32;
#pragma unroll
        for (int t = 0; t < 4; t++) {           // 1024 cp16
            int id   = tid + t * 256;
            int tile = id >> 9;                 // 0..1
            int r    = (id >> 2) & 127;
            int c    = id & 3;
            const __half* g = tile ? gB : gA;
            cp16(base + tile * S_TILE + r * PITCH + c * 16,
                 g + (size_t)r * K + k0 + c * 8);
        }
        CP_COMMIT();
    };

#pragma unroll
    for (int s = 0; s < SSTAGES - 1; s++) issue(s);   // 2 groups in flight

    const uint32_t lrow = (uint32_t)(lane & 15);
    const uint32_t lhal = (uint32_t)(lane >> 4) * 16;

    for (int it = 0; it < nk; it++) {
        asm volatile("cp.async.wait_group 1;" ::: "memory");   // oldest done
        __syncthreads();
        int pf = it + SSTAGES - 1;
        if (pf < nk) issue(pf); else CP_COMMIT();

        uint32_t stg = smb + (uint32_t)((unsigned)it % 3u) * S_STAGE;
#pragma unroll
        for (int k16 = 0; k16 < 2; k16++) {
            uint32_t koff = lhal + (uint32_t)k16 * 32;
            uint32_t ah[2][4];
#pragma unroll
            for (int mi = 0; mi < 2; mi++) {
                uint32_t ro = (uint32_t)(wm * 32 + mi * 16) + lrow;
                ldsm4(ah[mi], stg + ro * PITCH + koff);
            }
            uint32_t bh[8][2];
#pragma unroll
            for (int jj = 0; jj < 4; jj++) {
                uint32_t ro = (uint32_t)(wn * 64 + jj * 16) + lrow;
                uint32_t r4[4];
                ldsm4(r4, stg + S_TILE + ro * PITCH + koff);
                bh[jj * 2][0] = r4[0]; bh[jj * 2][1] = r4[2];
                bh[jj * 2 + 1][0] = r4[1]; bh[jj * 2 + 1][1] = r4[3];
            }
#pragma unroll
            for (int mi = 0; mi < 2; mi++)
#pragma unroll
                for (int nj = 0; nj < 8; nj++) hmma(acc[mi][nj], ah[mi], bh[nj]);
        }
    }

    // ---- 1-of-8 select epilogue ----
    const int rr = lane >> 2;
    const int q2 = (lane & 3) * 2;
#pragma unroll
    for (int mi = 0; mi < 2; mi++) {
        int r_lo = row0 + wm * 32 + mi * 16 + rr;
        int r_hi = r_lo + 8;
#pragma unroll
        for (int nj = 0; nj < 8; nj++) {
            int o   = (col0 + wn * 64 + nj * 8) >> 3;
            int cb0 = ctx[(size_t)r_lo * O + o] & 7;
            int cb1 = ctx[(size_t)r_hi * O + o] & 7;
            if (cb0 == q2 || cb0 == q2 + 1) {
                float v = (cb0 == q2) ? acc[mi][nj][0] : acc[mi][nj][1];
                if (bias) v += bias[o * 8 + cb0];
                size_t idx = (size_t)r_lo * O + o;
                if (MODE == 1) outh[idx] = __float2half_rn(v);
                else           outf[idx] = v;
            }
            if (cb1 == q2 || cb1 == q2 + 1) {
                float v = (cb1 == q2) ? acc[mi][nj][2] : acc[mi][nj][3];
                if (bias) v += bias[o * 8 + cb1];
                size_t idx = (size_t)r_hi * O + o;
                if (MODE == 1) outh[idx] = __float2half_rn(v);
                else           outf[idx] = v;
            }
        }
    }
}

// ============================ host =========================================
extern "C" void kernel_launch(void* const* d_in, const int* in_sizes, int n_in,
                              void* d_out, int out_size)
{
    const float* x  = (const float*)d_in[0];
    const float* W0 = (const float*)d_in[1];
    const float* W1 = (const float*)d_in[2];
    const float* W2 = (const float*)d_in[3];
    const float* b1 = (const float*)d_in[4];
    const float* b2 = (const float*)d_in[5];
    const float* H0 = (const float*)d_in[6];
    const float* T0 = (const float*)d_in[7];
    const float* H1 = (const float*)d_in[8];
    const float* T1 = (const float*)d_in[9];
    const float* H2 = (const float*)d_in[10];
    const float* T2 = (const float*)d_in[11];
    float* out = (float*)d_out;

    void *pxh, *pa, *pb, *pwa, *pwb, *pc0, *pc1, *pc2;
    cudaGetSymbolAddress(&pxh, g_xh);
    cudaGetSymbolAddress(&pa,  g_hA);  cudaGetSymbolAddress(&pb,  g_hB);
    cudaGetSymbolAddress(&pwa, g_whA); cudaGetSymbolAddress(&pwb, g_whB);
    cudaGetSymbolAddress(&pc0, g_ctx0); cudaGetSymbolAddress(&pc1, g_ctx1);
    cudaGetSymbolAddress(&pc2, g_ctx2);
    __half* xh  = (__half*)pxh;
    __half* hA  = (__half*)pa;   __half* hB  = (__half*)pb;
    __half* whA = (__half*)pwa;  __half* whB = (__half*)pwb;
    unsigned char* c0 = (unsigned char*)pc0;
    unsigned char* c1 = (unsigned char*)pc1;
    unsigned char* c2 = (unsigned char*)pc2;

    const int B = 4096, DIN = 1024, DLAT = 2048, DOUT = 1024;

    cudaFuncSetAttribute(gemm_ctx,    cudaFuncAttributeMaxDynamicSharedMemorySize, C_SMEM);
    cudaFuncSetAttribute(gemm_sel<1>, cudaFuncAttributeMaxDynamicSharedMemorySize, S_SMEM);
    cudaFuncSetAttribute(gemm_sel<2>, cudaFuncAttributeMaxDynamicSharedMemorySize, S_SMEM);

    auto conv = [](const float* in, __half* dst, size_t n) {
        int n4 = (int)(n / 4);
        conv_hi<<<(n4 + 255) / 256, 256>>>(in, dst, n4);
    };

    // Launch order keeps the profiled launch (0-based #3) on gemm_ctx.
    conv(x,  xh,  (size_t)B * DIN);                                  // 0
    conv(H0, whA, (size_t)DLAT * 3 * DIN);                           // 1
    conv(W0, whB, (size_t)DLAT * 8 * DIN);                           // 2
    gemm_ctx<<<dim3(B / 128, (DLAT * 3) / 192), 256, C_SMEM>>>(      // 3
        xh, whA, DIN, DLAT, c0, T0, x, H0);
    gemm_sel<1><<<dim3(B / 128, (DLAT * 8) / 128), 256, S_SMEM>>>(   // 4
        xh, whB, DIN, DLAT, c0, nullptr, nullptr, hA);

    conv(H1, whA, (size_t)DLAT * 3 * DIN);                           // 5
    gemm_ctx<<<dim3(B / 128, (DLAT * 3) / 192), 256, C_SMEM>>>(      // 6
        xh, whA, DIN, DLAT, c1, T1, x, H1);
    conv(W1, whB, (size_t)DLAT * 8 * DLAT);                          // 7
    gemm_sel<1><<<dim3(B / 128, (DLAT * 8) / 128), 256, S_SMEM>>>(   // 8
        hA, whB, DLAT, DLAT, c1, b1, nullptr, hB);

    conv(H2, whA, (size_t)DOUT * 3 * DIN);                           // 9
    gemm_ctx<<<dim3(B / 128, (DOUT * 3) / 192), 256, C_SMEM>>>(      // 10
        xh, whA, DIN, DOUT, c2, T2, x, H2);
    conv(W2, whB, (size_t)DOUT * 8 * DLAT);                          // 11
    gemm_sel<2><<<dim3(B / 128, (DOUT * 8) / 128), 256, S_SMEM>>>(   // 12
        hB, whB, DLAT, DOUT, c2, b2, out, nullptr);

    (void)in_sizes; (void)n_in; (void)out_size;
}

// round 12
// speedup vs baseline: 1.0004x; 1.0004x over previous
#include <cuda_runtime.h>
#include <cuda_fp16.h>
#include <cstdint>
#include <cstddef>
#include <math.h>

// ---------------------------------------------------------------------------
// GLN_56006373539841: HMMA fp16 GEMM, single-pass (R10 config).
// R12: ctx epilogue pushes flagged entries to a COMPACT GLOBAL QUEUE;
//      standalone rescue kernel processes the queue warp-per-entry with
//      full-chip parallelism (no 8MB scan, no sparse ballots).
//   B=4096, D_IN=1024, D_LAT=2048, D_OUT=1024, SHATTER=3, NC=8
// ---------------------------------------------------------------------------

#define RESCUE_TAU 0.08f
#define PITCH   80                    // 64B data + 16B pad (KC=32 fp16 rows)
#define RQ_CAP  131072                // global rescue queue capacity

// select GEMM (NT=128): 2 tiles (A, B), 3 stages -> 2 CTAs/SM
#define SSTAGES 3
#define S_TILE  (128 * PITCH)         // 10240
#define S_STAGE (2 * S_TILE)          // 20480
#define S_SMEM  (SSTAGES * S_STAGE)   // 61440

// ctx GEMM (NT=192): 2 tiles (A, B), 4 stages (1 CTA/SM, reg-heavy)
#define CSTAGES 4
#define C_AB    (128 * PITCH)         // 10240
#define C_BB    (192 * PITCH)         // 15360
#define C_STAGE (C_AB + C_BB)         // 25600
#define C_SMEM  (CSTAGES * C_STAGE)   // 102400
#define SC_PITCH 194                  // score staging pitch (floats)

// ============================ PTX helpers ==================================
__device__ __forceinline__ uint32_t smem_u32(const void* p) {
    uint32_t a;
    asm("{ .reg .u64 t; cvta.to.shared.u64 t, %1; cvt.u32.u64 %0, t; }"
        : "=r"(a) : "l"(p));
    return a;
}
__device__ __forceinline__ void cp16(uint32_t dst, const void* src) {
    asm volatile("cp.async.cg.shared.global [%0], [%1], 16;" :: "r"(dst), "l"(src));
}
#define CP_COMMIT() asm volatile("cp.async.commit_group;" ::: "memory")

__device__ __forceinline__ void ldsm4(uint32_t* r, uint32_t addr) {
    asm volatile("ldmatrix.sync.aligned.m8n8.x4.shared.b16 {%0,%1,%2,%3}, [%4];"
        : "=r"(r[0]), "=r"(r[1]), "=r"(r[2]), "=r"(r[3]) : "r"(addr));
}
__device__ __forceinline__ void hmma(float* d, const uint32_t* a, const uint32_t* b) {
    asm volatile("mma.sync.aligned.m16n8k16.row.col.f32.f16.f16.f32 "
        "{%0,%1,%2,%3},{%4,%5,%6,%7},{%8,%9},{%0,%1,%2,%3};"
        : "+f"(d[0]), "+f"(d[1]), "+f"(d[2]), "+f"(d[3])
        : "r"(a[0]), "r"(a[1]), "r"(a[2]), "r"(a[3]), "r"(b[0]), "r"(b[1]));
}

// ============================ scratch ======================================
__device__ __half g_xh [4096u * 1024u];
__device__ __half g_hA [4096u * 2048u];
__device__ __half g_hB [4096u * 2048u];
__device__ __half g_whA[6144u * 1024u];     // H conversions (contexts)
__device__ __half g_whB[16384u * 2048u];    // W conversions (largest: W1)
__device__ unsigned char g_ctx0[4096u * 2048u];
__device__ unsigned char g_ctx1[4096u * 2048u];
__device__ unsigned char g_ctx2[4096u * 1024u];
__device__ uint32_t g_rq[RQ_CAP];           // rescue queue (reused per layer)
__device__ int      g_cnt[4];               // per-layer rescue counters

// ============================ tiny kernels =================================
__global__ void zero_counters(int* cnt) {
    if (threadIdx.x < 4) cnt[threadIdx.x] = 0;
}

__global__ void conv_hi(const float* __restrict__ in, __half* __restrict__ hi, int n4)
{
    int i = blockIdx.x * blockDim.x + threadIdx.x;
    if (i >= n4) return;
    float4 v = ((const float4*)in)[i];
    ((__half2*)hi)[i * 2 + 0] = __halves2half2(__float2half_rn(v.x), __float2half_rn(v.y));
    ((__half2*)hi)[i * 2 + 1] = __halves2half2(__float2half_rn(v.z), __float2half_rn(v.w));
}

// ============================ ctx GEMM (fused combine + queue push) ========
// CTA 128M x 192N, 8 warps (4M x 2N), warp tile 32x96.  (R10 mainloop)
// Epilogue: ctx bytes (index only) + flagged entries -> global queue.
// Entry pack: b[0:12) | o[12:23) | c[23:26) | fm[26:29)
__global__ __launch_bounds__(256, 1)
void gemm_ctx(const __half* __restrict__ Ahi, const __half* __restrict__ Bhi,
              int K, int O,
              unsigned char* __restrict__ ctxout, const float* __restrict__ T,
              uint32_t* __restrict__ rq, int* __restrict__ cnt)
{
    extern __shared__ char smraw[];
    const uint32_t smb = smem_u32(smraw);
    const int tid  = threadIdx.x;
    const int lane = tid & 31;
    const int wid  = tid >> 5;
    const int wm   = wid & 3;
    const int wn   = wid >> 2;
    const int row0 = blockIdx.x * 128;
    const int col0 = blockIdx.y * 192;

    const __half* gA = Ahi + (size_t)row0 * K;
    const __half* gB = Bhi + (size_t)col0 * K;

    float acc[2][12][4];
#pragma unroll
    for (int i = 0; i < 2; i++)
#pragma unroll
        for (int j = 0; j < 12; j++)
#pragma unroll
            for (int q = 0; q < 4; q++) acc[i][j][q] = 0.0f;

    const int nk = K >> 5;

    auto issue = [&](int s) {
        uint32_t base = smb + (uint32_t)(s & (CSTAGES - 1)) * C_STAGE;
        int k0 = s * 32;
#pragma unroll
        for (int t = 0; t < 2; t++) {           // A: 512 cp16
            int id = tid + t * 256;
            int r  = id >> 2, c = id & 3;
            cp16(base + r * PITCH + c * 16, gA + (size_t)r * K + k0 + c * 8);
        }
#pragma unroll
        for (int t = 0; t < 3; t++) {           // B: 768 cp16
            int id = tid + t * 256;
            int r  = id >> 2, c = id & 3;
            cp16(base + C_AB + r * PITCH + c * 16, gB + (size_t)r * K + k0 + c * 8);
        }
        CP_COMMIT();
    };

#pragma unroll
    for (int s = 0; s < CSTAGES - 1; s++) issue(s);

    const uint32_t lrow = (uint32_t)(lane & 15);
    const uint32_t lhal = (uint32_t)(lane >> 4) * 16;

    for (int it = 0; it < nk; it++) {
        asm volatile("cp.async.wait_group 2;" ::: "memory");
        __syncthreads();
        int pf = it + CSTAGES - 1;
        if (pf < nk) issue(pf); else CP_COMMIT();

        uint32_t stg = smb + (uint32_t)(it & (CSTAGES - 1)) * C_STAGE;
#pragma unroll
        for (int k16 = 0; k16 < 2; k16++) {
            uint32_t koff = lhal + (uint32_t)k16 * 32;
            uint32_t ah[2][4];
#pragma unroll
            for (int mi = 0; mi < 2; mi++) {
                uint32_t ro = (uint32_t)(wm * 32 + mi * 16) + lrow;
                ldsm4(ah[mi], stg + ro * PITCH + koff);
            }
            uint32_t bh[12][2];
#pragma unroll
            for (int jj = 0; jj < 6; jj++) {
                uint32_t ro = (uint32_t)(wn * 96 + jj * 16) + lrow;
                uint32_t r4[4];
                ldsm4(r4, stg + C_AB + ro * PITCH + koff);
                bh[jj * 2][0] = r4[0]; bh[jj * 2][1] = r4[2];
                bh[jj * 2 + 1][0] = r4[1]; bh[jj * 2 + 1][1] = r4[3];
            }
#pragma unroll
            for (int mi = 0; mi < 2; mi++)
#pragma unroll
                for (int nj = 0; nj < 12; nj++) hmma(acc[mi][nj], ah[mi], bh[nj]);
        }
    }
    asm volatile("cp.async.wait_group 0;" ::: "memory");
    __syncthreads();

    // ---- stage scores into smem ----
    float* ssc = (float*)smraw;
    const int rr = lane >> 2;
    const int q2 = (lane & 3) * 2;
#pragma unroll
    for (int mi = 0; mi < 2; mi++) {
        int r_lo = wm * 32 + mi * 16 + rr;
        int r_hi = r_lo + 8;
#pragma unroll
        for (int nj = 0; nj < 12; nj++) {
            int c = wn * 96 + nj * 8 + q2;
            *(float2*)&ssc[r_lo * SC_PITCH + c] = make_float2(acc[mi][nj][0], acc[mi][nj][1]);
            *(float2*)&ssc[r_hi * SC_PITCH + c] = make_float2(acc[mi][nj][2], acc[mi][nj][3]);
        }
    }
    __syncthreads();

    // ---- combine: 128 rows x 64 o-groups; push flagged to global queue ----
    const int oc0 = col0 / 3;
#pragma unroll
    for (int w8 = 0; w8 < 8; w8++) {
        int word_id = tid + w8 * 256;
        int r  = word_id >> 4;
        int wo = word_id & 15;
        const float* sp = ssc + r * SC_PITCH + wo * 12;
        uint32_t word = 0;
#pragma unroll
        for (int j = 0; j < 4; j++) {
            int o = oc0 + wo * 4 + j;
            int c = 0, fm = 0;
#pragma unroll
            for (int s = 0; s < 3; s++) {
                float th = __ldg(T + o * 3 + s);
                float d  = sp[j * 3 + s] - th;
                c  |= ((int)(d > 0.0f)) << s;
                fm |= ((int)(fabsf(d) < RESCUE_TAU)) << s;
            }
            if (fm) {
                int slot = atomicAdd(cnt, 1);
                if (slot < RQ_CAP)
                    rq[slot] = (uint32_t)(row0 + r) | ((uint32_t)o << 12) |
                               ((uint32_t)c << 23) | ((uint32_t)fm << 26);
            }
            word |= (uint32_t)((unsigned char)c) << (j * 8);
        }
        *(uint32_t*)(ctxout + (size_t)(row0 + r) * O + oc0 + wo * 4) = word;
    }
}

// ============================ dense fp64 rescue ============================
// Warp-per-entry over the compacted queue; no scanning.
__global__ void gln_rescue(const uint32_t* __restrict__ rq, const int* __restrict__ cnt,
                           unsigned char* __restrict__ ctx,
                           const float* __restrict__ z, const float* __restrict__ H,
                           const float* __restrict__ T, int O, int K)
{
    const int lane = threadIdx.x & 31;
    const int gw   = (blockIdx.x * blockDim.x + threadIdx.x) >> 5;
    const int nw   = (gridDim.x * blockDim.x) >> 5;
    int n = *cnt; if (n > RQ_CAP) n = RQ_CAP;

    for (int q = gw; q < n; q += nw) {
        uint32_t e = rq[q];
        int b  = (int)(e & 0xFFFu);
        int o  = (int)((e >> 12) & 0x7FFu);
        int c  = (int)((e >> 23) & 7u);
        int fm = (int)((e >> 26) & 7u);
        const float* zr = z + (size_t)b * K;
#pragma unroll
        for (int s = 0; s < 3; s++) {
            if (!(fm & (1 << s))) continue;
            const float* hr = H + (size_t)(o * 3 + s) * K;
            double p0 = 0.0, p1 = 0.0;
            for (int k = lane; k < K; k += 64) {
                p0 += (double)zr[k]      * (double)hr[k];
                p1 += (double)zr[k + 32] * (double)hr[k + 32];
            }
            double part = p0 + p1;
#pragma unroll
            for (int off = 16; off; off >>= 1)
                part += __shfl_down_sync(0xFFFFFFFFu, part, off);
            part = __shfl_sync(0xFFFFFFFFu, part, 0);
            c = (c & ~(1 << s)) | (((int)(part > (double)__ldg(T + o * 3 + s))) << s);
        }
        if (lane == 0) ctx[(size_t)b * O + o] = (unsigned char)c;
    }
}

// ============================ select GEMM ==================================
// CTA 128x128, 8 warps (4M x 2N), warp tile 32x64.  3-stage smem + 2 CTAs/SM.
// MODE 1: hidden -> fp16.  MODE 2: final -> fp32.
template <int MODE>
__global__ __launch_bounds__(256, 2)
void gemm_sel(const __half* __restrict__ Ahi, const __half* __restrict__ Bhi,
              int K, int O,
              const unsigned char* __restrict__ ctx, const float* __restrict__ bias,
              float* __restrict__ outf, __half* __restrict__ outh)
{
    extern __shared__ char smraw[];
    const uint32_t smb = smem_u32(smraw);
    const int tid  = threadIdx.x;
    const int lane = tid & 31;
    const int wid  = tid >> 5;
    const int wm   = wid & 3;
    const int wn   = wid >> 2;
    const int row0 = blockIdx.x * 128;
    const int col0 = blockIdx.y * 128;

    const __half* gA = Ahi + (size_t)row0 * K;
    const __half* gB = Bhi + (size_t)col0 * K;

    float acc[2][8][4];
#pragma unroll
    for (int i = 0; i < 2; i++)
#pragma unroll
        for (int j = 0; j < 8; j++)
#pragma unroll
            for (int q = 0; q < 4; q++) acc[i][j][q] = 0.0f;

    const int nk = K >> 5;

    auto issue = [&](int s) {
        uint32_t base = smb + (uint32_t)((unsigned)s % 3u) * S_STAGE;
        int k0 = s * 32;
#pragma unroll
        for (int t = 0; t < 4; t++) {           // 1024 cp16
            int id   = tid + t * 256;
            int tile = id >> 9;                 // 0..1
            int r    = (id >> 2) & 127;
            int c    = id & 3;
            const __half* g = tile ? gB : gA;
            cp16(base + tile * S_TILE + r * PITCH + c * 16,
                 g + (size_t)r * K + k0 + c * 8);
        }
        CP_COMMIT();
    };

#pragma unroll
    for (int s = 0; s < SSTAGES - 1; s++) issue(s);   // 2 groups in flight

    const uint32_t lrow = (uint32_t)(lane & 15);
    const uint32_t lhal = (uint32_t)(lane >> 4) * 16;

    for (int it = 0; it < nk; it++) {
        asm volatile("cp.async.wait_group 1;" ::: "memory");   // oldest done
        __syncthreads();
        int pf = it + SSTAGES - 1;
        if (pf < nk) issue(pf); else CP_COMMIT();

        uint32_t stg = smb + (uint32_t)((unsigned)it % 3u) * S_STAGE;
#pragma unroll
        for (int k16 = 0; k16 < 2; k16++) {
            uint32_t koff = lhal + (uint32_t)k16 * 32;
            uint32_t ah[2][4];
#pragma unroll
            for (int mi = 0; mi < 2; mi++) {
                uint32_t ro = (uint32_t)(wm * 32 + mi * 16) + lrow;
                ldsm4(ah[mi], stg + ro * PITCH + koff);
            }
            uint32_t bh[8][2];
#pragma unroll
            for (int jj = 0; jj < 4; jj++) {
                uint32_t ro = (uint32_t)(wn * 64 + jj * 16) + lrow;
                uint32_t r4[4];
                ldsm4(r4, stg + S_TILE + ro * PITCH + koff);
                bh[jj * 2][0] = r4[0]; bh[jj * 2][1] = r4[2];
                bh[jj * 2 + 1][0] = r4[1]; bh[jj * 2 + 1][1] = r4[3];
            }
#pragma unroll
            for (int mi = 0; mi < 2; mi++)
#pragma unroll
                for (int nj = 0; nj < 8; nj++) hmma(acc[mi][nj], ah[mi], bh[nj]);
        }
    }

    // ---- 1-of-8 select epilogue ----
    const int rr = lane >> 2;
    const int q2 = (lane & 3) * 2;
#pragma unroll
    for (int mi = 0; mi < 2; mi++) {
        int r_lo = row0 + wm * 32 + mi * 16 + rr;
        int r_hi = r_lo + 8;
#pragma unroll
        for (int nj = 0; nj < 8; nj++) {
            int o   = (col0 + wn * 64 + nj * 8) >> 3;
            int cb0 = ctx[(size_t)r_lo * O + o] & 7;
            int cb1 = ctx[(size_t)r_hi * O + o] & 7;
            if (cb0 == q2 || cb0 == q2 + 1) {
                float v = (cb0 == q2) ? acc[mi][nj][0] : acc[mi][nj][1];
                if (bias) v += bias[o * 8 + cb0];
                size_t idx = (size_t)r_lo * O + o;
                if (MODE == 1) outh[idx] = __float2half_rn(v);
                else           outf[idx] = v;
            }
            if (cb1 == q2 || cb1 == q2 + 1) {
                float v = (cb1 == q2) ? acc[mi][nj][2] : acc[mi][nj][3];
                if (bias) v += bias[o * 8 + cb1];
                size_t idx = (size_t)r_hi * O + o;
                if (MODE == 1) outh[idx] = __float2half_rn(v);
                else           outf[idx] = v;
            }
        }
    }
}

// ============================ host =========================================
extern "C" void kernel_launch(void* const* d_in, const int* in_sizes, int n_in,
                              void* d_out, int out_size)
{
    const float* x  = (const float*)d_in[0];
    const float* W0 = (const float*)d_in[1];
    const float* W1 = (const float*)d_in[2];
    const float* W2 = (const float*)d_in[3];
    const float* b1 = (const float*)d_in[4];
    const float* b2 = (const float*)d_in[5];
    const float* H0 = (const float*)d_in[6];
    const float* T0 = (const float*)d_in[7];
    const float* H1 = (const float*)d_in[8];
    const float* T1 = (const float*)d_in[9];
    const float* H2 = (const float*)d_in[10];
    const float* T2 = (const float*)d_in[11];
    float* out = (float*)d_out;

    void *pxh, *pa, *pb, *pwa, *pwb, *pc0, *pc1, *pc2, *prq, *pcnt;
    cudaGetSymbolAddress(&pxh, g_xh);
    cudaGetSymbolAddress(&pa,  g_hA);  cudaGetSymbolAddress(&pb,  g_hB);
    cudaGetSymbolAddress(&pwa, g_whA); cudaGetSymbolAddress(&pwb, g_whB);
    cudaGetSymbolAddress(&pc0, g_ctx0); cudaGetSymbolAddress(&pc1, g_ctx1);
    cudaGetSymbolAddress(&pc2, g_ctx2);
    cudaGetSymbolAddress(&prq, g_rq);  cudaGetSymbolAddress(&pcnt, g_cnt);
    __half* xh  = (__half*)pxh;
    __half* hA  = (__half*)pa;   __half* hB  = (__half*)pb;
    __half* whA = (__half*)pwa;  __half* whB = (__half*)pwb;
    unsigned char* c0 = (unsigned char*)pc0;
    unsigned char* c1 = (unsigned char*)pc1;
    unsigned char* c2 = (unsigned char*)pc2;
    uint32_t* rq = (uint32_t*)prq;
    int*      cn = (int*)pcnt;

    const int B = 4096, DIN = 1024, DLAT = 2048, DOUT = 1024;

    cudaFuncSetAttribute(gemm_ctx,    cudaFuncAttributeMaxDynamicSharedMemorySize, C_SMEM);
    cudaFuncSetAttribute(gemm_sel<1>, cudaFuncAttributeMaxDynamicSharedMemorySize, S_SMEM);
    cudaFuncSetAttribute(gemm_sel<2>, cudaFuncAttributeMaxDynamicSharedMemorySize, S_SMEM);

    auto conv = [](const float* in, __half* dst, size_t n) {
        int n4 = (int)(n / 4);
        conv_hi<<<(n4 + 255) / 256, 256>>>(in, dst, n4);
    };

    // Launch order keeps the profiled launch (0-based #3) on gemm_ctx.
    zero_counters<<<1, 32>>>(cn);                                    // 0
    conv(x,  xh,  (size_t)B * DIN);                                  // 1
    conv(H0, whA, (size_t)DLAT * 3 * DIN);                           // 2
    gemm_ctx<<<dim3(B / 128, (DLAT * 3) / 192), 256, C_SMEM>>>(      // 3
        xh, whA, DIN, DLAT, c0, T0, rq, cn + 0);
    gln_rescue<<<1024, 256>>>(rq, cn + 0, c0, x, H0, T0, DLAT, DIN); // 4
    conv(W0, whB, (size_t)DLAT * 8 * DIN);                           // 5
    gemm_sel<1><<<dim3(B / 128, (DLAT * 8) / 128), 256, S_SMEM>>>(   // 6
        xh, whB, DIN, DLAT, c0, nullptr, nullptr, hA);

    conv(H1, whA, (size_t)DLAT * 3 * DIN);                           // 7
    gemm_ctx<<<dim3(B / 128, (DLAT * 3) / 192), 256, C_SMEM>>>(      // 8
        xh, whA, DIN, DLAT, c1, T1, rq, cn + 1);
    gln_rescue<<<1024, 256>>>(rq, cn + 1, c1, x, H1, T1, DLAT, DIN); // 9
    conv(W1, whB, (size_t)DLAT * 8 * DLAT);                          // 10
    gemm_sel<1><<<dim3(B / 128, (DLAT * 8) / 128), 256, S_SMEM>>>(   // 11
        hA, whB, DLAT, DLAT, c1, b1, nullptr, hB);

    conv(H2, whA, (size_t)DOUT * 3 * DIN);                           // 12
    gemm_ctx<<<dim3(B / 128, (DOUT * 3) / 192), 256, C_SMEM>>>(      // 13
        xh, whA, DIN, DOUT, c2, T2, rq, cn + 2);
    gln_rescue<<<1024, 256>>>(rq, cn + 2, c2, x, H2, T2, DOUT, DIN); // 14
    conv(W2, whB, (size_t)DOUT * 8 * DLAT);                          // 15
    gemm_sel<2><<<dim3(B / 128, (DOUT * 8) / 128), 256, S_SMEM>>>(   // 16
        hB, whB, DLAT, DOUT, c2, b2, out, nullptr);

    (void)in_sizes; (void)n_in; (void)out_size;
}

// round 14
// speedup vs baseline: 1.0764x; 1.0760x over previous
#include <cuda_runtime.h>
#include <cuda_fp16.h>
#include <cstdint>
#include <cstddef>
#include <math.h>

// ---------------------------------------------------------------------------
// GLN_56006373539841: HMMA fp16 GEMM, single-pass (R10 kernels, byte-identical).
// R14: stream-forked CUDA graph with CORRECT capture protocol: fork event is
//      recorded on the capture stream first; every side stream joins via
//      cudaStreamWaitEvent before launching anything (R13 violated this).
//   B=4096, D_IN=1024, D_LAT=2048, D_OUT=1024, SHATTER=3, NC=8
// ---------------------------------------------------------------------------

#define RESCUE_TAU 0.08f
#define PITCH   80                    // 64B data + 16B pad (KC=32 fp16 rows)

// select GEMM (NT=128): 2 tiles (A, B), 3 stages -> 2 CTAs/SM
#define SSTAGES 3
#define S_TILE  (128 * PITCH)         // 10240
#define S_STAGE (2 * S_TILE)          // 20480
#define S_SMEM  (SSTAGES * S_STAGE)   // 61440

// ctx GEMM (NT=192): 2 tiles (A, B), 4 stages (1 CTA/SM, reg-heavy)
#define CSTAGES 4
#define C_AB    (128 * PITCH)         // 10240
#define C_BB    (192 * PITCH)         // 15360
#define C_STAGE (C_AB + C_BB)         // 25600
#define C_SMEM  (CSTAGES * C_STAGE)   // 102400
#define SC_PITCH 194                  // score staging pitch (floats)

// ============================ PTX helpers ==================================
__device__ __forceinline__ uint32_t smem_u32(const void* p) {
    uint32_t a;
    asm("{ .reg .u64 t; cvta.to.shared.u64 t, %1; cvt.u32.u64 %0, t; }"
        : "=r"(a) : "l"(p));
    return a;
}
__device__ __forceinline__ void cp16(uint32_t dst, const void* src) {
    asm volatile("cp.async.cg.shared.global [%0], [%1], 16;" :: "r"(dst), "l"(src));
}
#define CP_COMMIT() asm volatile("cp.async.commit_group;" ::: "memory")

__device__ __forceinline__ void ldsm4(uint32_t* r, uint32_t addr) {
    asm volatile("ldmatrix.sync.aligned.m8n8.x4.shared.b16 {%0,%1,%2,%3}, [%4];"
        : "=r"(r[0]), "=r"(r[1]), "=r"(r[2]), "=r"(r[3]) : "r"(addr));
}
__device__ __forceinline__ void hmma(float* d, const uint32_t* a, const uint32_t* b) {
    asm volatile("mma.sync.aligned.m16n8k16.row.col.f32.f16.f16.f32 "
        "{%0,%1,%2,%3},{%4,%5,%6,%7},{%8,%9},{%0,%1,%2,%3};"
        : "+f"(d[0]), "+f"(d[1]), "+f"(d[2]), "+f"(d[3])
        : "r"(a[0]), "r"(a[1]), "r"(a[2]), "r"(a[3]), "r"(b[0]), "r"(b[1]));
}

// ============================ scratch ======================================
__device__ __half g_xh  [4096u * 1024u];
__device__ __half g_hA  [4096u * 2048u];
__device__ __half g_hB  [4096u * 2048u];
__device__ __half g_whA0[6144u * 1024u];    // H0 fp16
__device__ __half g_whA1[6144u * 1024u];    // H1 fp16
__device__ __half g_whA2[3072u * 1024u];    // H2 fp16
__device__ __half g_wh0 [16384u * 1024u];   // W0 fp16
__device__ __half g_wh1 [16384u * 2048u];   // W1 fp16
__device__ __half g_wh2 [8192u  * 2048u];   // W2 fp16
__device__ unsigned char g_ctx0[4096u * 2048u];
__device__ unsigned char g_ctx1[4096u * 2048u];
__device__ unsigned char g_ctx2[4096u * 1024u];

// ============================ convert kernel ===============================
__global__ void conv_hi(const float* __restrict__ in, __half* __restrict__ hi, int n4)
{
    int i = blockIdx.x * blockDim.x + threadIdx.x;
    if (i >= n4) return;
    float4 v = ((const float4*)in)[i];
    ((__half2*)hi)[i * 2 + 0] = __halves2half2(__float2half_rn(v.x), __float2half_rn(v.y));
    ((__half2*)hi)[i * 2 + 1] = __halves2half2(__float2half_rn(v.z), __float2half_rn(v.w));
}

// ============================ ctx GEMM (fused combine) =====================
// CTA 128M x 192N, 8 warps (4M x 2N), warp tile 32x96.  (R10, byte-identical)
// Output byte: bits 0-2 ctx index, bits 3-5 per-score rescue flags.
__global__ __launch_bounds__(256, 1)
void gemm_ctx(const __half* __restrict__ Ahi, const __half* __restrict__ Bhi,
              int K, int O,
              unsigned char* __restrict__ ctxout, const float* __restrict__ T)
{
    extern __shared__ char smraw[];
    const uint32_t smb = smem_u32(smraw);
    const int tid  = threadIdx.x;
    const int lane = tid & 31;
    const int wid  = tid >> 5;
    const int wm   = wid & 3;
    const int wn   = wid >> 2;
    const int row0 = blockIdx.x * 128;
    const int col0 = blockIdx.y * 192;

    const __half* gA = Ahi + (size_t)row0 * K;
    const __half* gB = Bhi + (size_t)col0 * K;

    float acc[2][12][4];
#pragma unroll
    for (int i = 0; i < 2; i++)
#pragma unroll
        for (int j = 0; j < 12; j++)
#pragma unroll
            for (int q = 0; q < 4; q++) acc[i][j][q] = 0.0f;

    const int nk = K >> 5;

    auto issue = [&](int s) {
        uint32_t base = smb + (uint32_t)(s & (CSTAGES - 1)) * C_STAGE;
        int k0 = s * 32;
#pragma unroll
        for (int t = 0; t < 2; t++) {           // A: 512 cp16
            int id = tid + t * 256;
            int r  = id >> 2, c = id & 3;
            cp16(base + r * PITCH + c * 16, gA + (size_t)r * K + k0 + c * 8);
        }
#pragma unroll
        for (int t = 0; t < 3; t++) {           // B: 768 cp16
            int id = tid + t * 256;
            int r  = id >> 2, c = id & 3;
            cp16(base + C_AB + r * PITCH + c * 16, gB + (size_t)r * K + k0 + c * 8);
        }
        CP_COMMIT();
    };

#pragma unroll
    for (int s = 0; s < CSTAGES - 1; s++) issue(s);

    const uint32_t lrow = (uint32_t)(lane & 15);
    const uint32_t lhal = (uint32_t)(lane >> 4) * 16;

    for (int it = 0; it < nk; it++) {
        asm volatile("cp.async.wait_group 2;" ::: "memory");
        __syncthreads();
        int pf = it + CSTAGES - 1;
        if (pf < nk) issue(pf); else CP_COMMIT();

        uint32_t stg = smb + (uint32_t)(it & (CSTAGES - 1)) * C_STAGE;
#pragma unroll
        for (int k16 = 0; k16 < 2; k16++) {
            uint32_t koff = lhal + (uint32_t)k16 * 32;
            uint32_t ah[2][4];
#pragma unroll
            for (int mi = 0; mi < 2; mi++) {
                uint32_t ro = (uint32_t)(wm * 32 + mi * 16) + lrow;
                ldsm4(ah[mi], stg + ro * PITCH + koff);
            }
            uint32_t bh[12][2];
#pragma unroll
            for (int jj = 0; jj < 6; jj++) {
                uint32_t ro = (uint32_t)(wn * 96 + jj * 16) + lrow;
                uint32_t r4[4];
                ldsm4(r4, stg + C_AB + ro * PITCH + koff);
                bh[jj * 2][0] = r4[0]; bh[jj * 2][1] = r4[2];
                bh[jj * 2 + 1][0] = r4[1]; bh[jj * 2 + 1][1] = r4[3];
            }
#pragma unroll
            for (int mi = 0; mi < 2; mi++)
#pragma unroll
                for (int nj = 0; nj < 12; nj++) hmma(acc[mi][nj], ah[mi], bh[nj]);
        }
    }
    asm volatile("cp.async.wait_group 0;" ::: "memory");
    __syncthreads();

    // ---- stage scores into smem ----
    float* ssc = (float*)smraw;
    const int rr = lane >> 2;
    const int q2 = (lane & 3) * 2;
#pragma unroll
    for (int mi = 0; mi < 2; mi++) {
        int r_lo = wm * 32 + mi * 16 + rr;
        int r_hi = r_lo + 8;
#pragma unroll
        for (int nj = 0; nj < 12; nj++) {
            int c = wn * 96 + nj * 8 + q2;
            *(float2*)&ssc[r_lo * SC_PITCH + c] = make_float2(acc[mi][nj][0], acc[mi][nj][1]);
            *(float2*)&ssc[r_hi * SC_PITCH + c] = make_float2(acc[mi][nj][2], acc[mi][nj][3]);
        }
    }
    __syncthreads();

    // ---- combine: 128 rows x 64 o-groups -> 2048 uint32 words ----
    const int oc0 = col0 / 3;
#pragma unroll
    for (int w8 = 0; w8 < 8; w8++) {
        int word_id = tid + w8 * 256;
        int r  = word_id >> 4;
        int wo = word_id & 15;
        const float* sp = ssc + r * SC_PITCH + wo * 12;
        uint32_t word = 0;
#pragma unroll
        for (int j = 0; j < 4; j++) {
            int o = oc0 + wo * 4 + j;
            int c = 0;
#pragma unroll
            for (int s = 0; s < 3; s++) {
                float th = __ldg(T + o * 3 + s);
                float d  = sp[j * 3 + s] - th;
                c |= ((int)(d > 0.0f)) << s;
                c |= ((int)(fabsf(d) < RESCUE_TAU)) << (3 + s);
            }
            word |= (uint32_t)((unsigned char)c) << (j * 8);
        }
        *(uint32_t*)(ctxout + (size_t)(row0 + r) * O + oc0 + wo * 4) = word;
    }
}

// ============================ warp-cooperative fp64 rescue =================
__global__ void gln_rescue(unsigned char* __restrict__ ctx,
                           const float* __restrict__ z,
                           const float* __restrict__ H,
                           const float* __restrict__ T,
                           int total4, int O, int K)
{
    int i    = blockIdx.x * blockDim.x + threadIdx.x;
    int lane = threadIdx.x & 31;
    uint32_t w = (i < total4) ? ((const uint32_t*)ctx)[i] : 0u;
    unsigned m = __ballot_sync(0xFFFFFFFFu, (w & 0x38383838u) != 0u);
    while (m) {
        int src = __ffs(m) - 1; m &= m - 1;
        uint32_t sw = __shfl_sync(0xFFFFFFFFu, w, src);
        int si = __shfl_sync(0xFFFFFFFFu, i, src);
#pragma unroll
        for (int j = 0; j < 4; j++) {
            uint32_t byte = (sw >> (j * 8)) & 0xFF;
            if (!(byte & 0x38)) continue;
            int idx = si * 4 + j;
            int b = idx / O, o = idx - b * O;
            const float* zr = z + (size_t)b * K;
            int c = (int)(byte & 7);
#pragma unroll
            for (int s = 0; s < 3; s++) {
                if (!(byte & (8u << s))) continue;
                const float* hr = H + (size_t)(o * 3 + s) * K;
                double p0 = 0.0, p1 = 0.0;
                for (int k = lane; k < K; k += 64) {
                    p0 += (double)zr[k]      * (double)hr[k];
                    p1 += (double)zr[k + 32] * (double)hr[k + 32];
                }
                double part = p0 + p1;
#pragma unroll
                for (int off = 16; off; off >>= 1)
                    part += __shfl_down_sync(0xFFFFFFFFu, part, off);
                part = __shfl_sync(0xFFFFFFFFu, part, 0);
                c = (c & ~(1 << s)) | (((int)(part > (double)T[o * 3 + s])) << s);
            }
            if (lane == 0) ctx[idx] = (unsigned char)c;
        }
    }
}

// ============================ select GEMM ==================================
// CTA 128x128, 8 warps (4M x 2N), warp tile 32x64.  3-stage smem + 2 CTAs/SM.
// MODE 1: hidden -> fp16.  MODE 2: final -> fp32.  (R10, byte-identical)
template <int MODE>
__global__ __launch_bounds__(256, 2)
void gemm_sel(const __half* __restrict__ Ahi, const __half* __restrict__ Bhi,
              int K, int O,
              const unsigned char* __restrict__ ctx, const float* __restrict__ bias,
              float* __restrict__ outf, __half* __restrict__ outh)
{
    extern __shared__ char smraw[];
    const uint32_t smb = smem_u32(smraw);
    const int tid  = threadIdx.x;
    const int lane = tid & 31;
    const int wid  = tid >> 5;
    const int wm   = wid & 3;
    const int wn   = wid >> 2;
    const int row0 = blockIdx.x * 128;
    const int col0 = blockIdx.y * 128;

    const __half* gA = Ahi + (size_t)row0 * K;
    const __half* gB = Bhi + (size_t)col0 * K;

    float acc[2][8][4];
#pragma unroll
    for (int i = 0; i < 2; i++)
#pragma unroll
        for (int j = 0; j < 8; j++)
#pragma unroll
            for (int q = 0; q < 4; q++) acc[i][j][q] = 0.0f;

    const int nk = K >> 5;

    auto issue = [&](int s) {
        uint32_t base = smb + (uint32_t)((unsigned)s % 3u) * S_STAGE;
        int k0 = s * 32;
#pragma unroll
        for (int t = 0; t < 4; t++) {           // 1024 cp16
            int id   = tid + t * 256;
            int tile = id >> 9;                 // 0..1
            int r    = (id >> 2) & 127;
            int c    = id & 3;
            const __half* g = tile ? gB : gA;
            cp16(base + tile * S_TILE + r * PITCH + c * 16,
                 g + (size_t)r * K + k0 + c * 8);
        }
        CP_COMMIT();
    };

#pragma unroll
    for (int s = 0; s < SSTAGES - 1; s++) issue(s);   // 2 groups in flight

    const uint32_t lrow = (uint32_t)(lane & 15);
    const uint32_t lhal = (uint32_t)(lane >> 4) * 16;

    for (int it = 0; it < nk; it++) {
        asm volatile("cp.async.wait_group 1;" ::: "memory");   // oldest done
        __syncthreads();
        int pf = it + SSTAGES - 1;
        if (pf < nk) issue(pf); else CP_COMMIT();

        uint32_t stg = smb + (uint32_t)((unsigned)it % 3u) * S_STAGE;
#pragma unroll
        for (int k16 = 0; k16 < 2; k16++) {
            uint32_t koff = lhal + (uint32_t)k16 * 32;
            uint32_t ah[2][4];
#pragma unroll
            for (int mi = 0; mi < 2; mi++) {
                uint32_t ro = (uint32_t)(wm * 32 + mi * 16) + lrow;
                ldsm4(ah[mi], stg + ro * PITCH + koff);
            }
            uint32_t bh[8][2];
#pragma unroll
            for (int jj = 0; jj < 4; jj++) {
                uint32_t ro = (uint32_t)(wn * 64 + jj * 16) + lrow;
                uint32_t r4[4];
                ldsm4(r4, stg + S_TILE + ro * PITCH + koff);
                bh[jj * 2][0] = r4[0]; bh[jj * 2][1] = r4[2];
                bh[jj * 2 + 1][0] = r4[1]; bh[jj * 2 + 1][1] = r4[3];
            }
#pragma unroll
            for (int mi = 0; mi < 2; mi++)
#pragma unroll
                for (int nj = 0; nj < 8; nj++) hmma(acc[mi][nj], ah[mi], bh[nj]);
        }
    }

    // ---- 1-of-8 select epilogue ----
    const int rr = lane >> 2;
    const int q2 = (lane & 3) * 2;
#pragma unroll
    for (int mi = 0; mi < 2; mi++) {
        int r_lo = row0 + wm * 32 + mi * 16 + rr;
        int r_hi = r_lo + 8;
#pragma unroll
        for (int nj = 0; nj < 8; nj++) {
            int o   = (col0 + wn * 64 + nj * 8) >> 3;
            int cb0 = ctx[(size_t)r_lo * O + o] & 7;
            int cb1 = ctx[(size_t)r_hi * O + o] & 7;
            if (cb0 == q2 || cb0 == q2 + 1) {
                float v = (cb0 == q2) ? acc[mi][nj][0] : acc[mi][nj][1];
                if (bias) v += bias[o * 8 + cb0];
                size_t idx = (size_t)r_lo * O + o;
                if (MODE == 1) outh[idx] = __float2half_rn(v);
                else           outf[idx] = v;
            }
            if (cb1 == q2 || cb1 == q2 + 1) {
                float v = (cb1 == q2) ? acc[mi][nj][2] : acc[mi][nj][3];
                if (bias) v += bias[o * 8 + cb1];
                size_t idx = (size_t)r_hi * O + o;
                if (MODE == 1) outh[idx] = __float2half_rn(v);
                else           outf[idx] = v;
            }
        }
    }
}

// ============================ host =========================================
extern "C" void kernel_launch(void* const* d_in, const int* in_sizes, int n_in,
                              void* d_out, int out_size)
{
    const float* x  = (const float*)d_in[0];
    const float* W0 = (const float*)d_in[1];
    const float* W1 = (const float*)d_in[2];
    const float* W2 = (const float*)d_in[3];
    const float* b1 = (const float*)d_in[4];
    const float* b2 = (const float*)d_in[5];
    const float* H0 = (const float*)d_in[6];
    const float* T0 = (const float*)d_in[7];
    const float* H1 = (const float*)d_in[8];
    const float* T1 = (const float*)d_in[9];
    const float* H2 = (const float*)d_in[10];
    const float* T2 = (const float*)d_in[11];
    float* out = (float*)d_out;

    void *p;
    cudaGetSymbolAddress(&p, g_xh);   __half* xh   = (__half*)p;
    cudaGetSymbolAddress(&p, g_hA);   __half* hA   = (__half*)p;
    cudaGetSymbolAddress(&p, g_hB);   __half* hB   = (__half*)p;
    cudaGetSymbolAddress(&p, g_whA0); __half* whA0 = (__half*)p;
    cudaGetSymbolAddress(&p, g_whA1); __half* whA1 = (__half*)p;
    cudaGetSymbolAddress(&p, g_whA2); __half* whA2 = (__half*)p;
    cudaGetSymbolAddress(&p, g_wh0);  __half* wh0  = (__half*)p;
    cudaGetSymbolAddress(&p, g_wh1);  __half* wh1  = (__half*)p;
    cudaGetSymbolAddress(&p, g_wh2);  __half* wh2  = (__half*)p;
    cudaGetSymbolAddress(&p, g_ctx0); unsigned char* c0 = (unsigned char*)p;
    cudaGetSymbolAddress(&p, g_ctx1); unsigned char* c1 = (unsigned char*)p;
    cudaGetSymbolAddress(&p, g_ctx2); unsigned char* c2 = (unsigned char*)p;

    const int B = 4096, DIN = 1024, DLAT = 2048, DOUT = 1024;

    // One-time resources (created on the first, uncaptured, correctness call).
    static cudaStream_t s1 = nullptr, s2 = nullptr, s3 = nullptr;
    static cudaEvent_t evFork, evX, evC1, evC2, evW0, evW1, evW2;
    static bool inited = false;
    if (!inited) {
        cudaStreamCreateWithFlags(&s1, cudaStreamNonBlocking);
        cudaStreamCreateWithFlags(&s2, cudaStreamNonBlocking);
        cudaStreamCreateWithFlags(&s3, cudaStreamNonBlocking);
        cudaEventCreateWithFlags(&evFork, cudaEventDisableTiming);
        cudaEventCreateWithFlags(&evX,    cudaEventDisableTiming);
        cudaEventCreateWithFlags(&evC1,   cudaEventDisableTiming);
        cudaEventCreateWithFlags(&evC2,   cudaEventDisableTiming);
        cudaEventCreateWithFlags(&evW0,   cudaEventDisableTiming);
        cudaEventCreateWithFlags(&evW1,   cudaEventDisableTiming);
        cudaEventCreateWithFlags(&evW2,   cudaEventDisableTiming);
        cudaFuncSetAttribute(gemm_ctx,    cudaFuncAttributeMaxDynamicSharedMemorySize, C_SMEM);
        cudaFuncSetAttribute(gemm_sel<1>, cudaFuncAttributeMaxDynamicSharedMemorySize, S_SMEM);
        cudaFuncSetAttribute(gemm_sel<2>, cudaFuncAttributeMaxDynamicSharedMemorySize, S_SMEM);
        inited = true;
    }

    auto conv = [](const float* in, __half* dst, size_t n, cudaStream_t st) {
        int n4 = (int)(n / 4);
        conv_hi<<<(n4 + 255) / 256, 256, 0, st>>>(in, dst, n4);
    };

    cudaStream_t s0 = 0;   // default (capture) stream

    // ---- fork: all side streams join capture BEFORE any of their work ----
    cudaEventRecord(evFork, s0);
    cudaStreamWaitEvent(s1, evFork, 0);
    cudaStreamWaitEvent(s2, evFork, 0);
    cudaStreamWaitEvent(s3, evFork, 0);

    // ---- s0: input convert ----
    conv(x, xh, (size_t)B * DIN, s0);
    cudaEventRecord(evX, s0);

    // ---- s3: all weight converts (independent of x) ----
    conv(W0, wh0, (size_t)DLAT * 8 * DIN, s3);
    cudaEventRecord(evW0, s3);
    conv(W1, wh1, (size_t)DLAT * 8 * DLAT, s3);
    cudaEventRecord(evW1, s3);
    conv(W2, wh2, (size_t)DOUT * 8 * DLAT, s3);
    cudaEventRecord(evW2, s3);

    // ---- s1: layer-1 context branch ----
    conv(H1, whA1, (size_t)DLAT * 3 * DIN, s1);
    cudaStreamWaitEvent(s1, evX, 0);
    gemm_ctx<<<dim3(B / 128, (DLAT * 3) / 192), 256, C_SMEM, s1>>>(
        xh, whA1, DIN, DLAT, c1, T1);
    gln_rescue<<<(B * DLAT / 4 + 255) / 256, 256, 0, s1>>>(
        c1, x, H1, T1, B * DLAT / 4, DLAT, DIN);
    cudaEventRecord(evC1, s1);

    // ---- s2: layer-2 context branch ----
    conv(H2, whA2, (size_t)DOUT * 3 * DIN, s2);
    cudaStreamWaitEvent(s2, evX, 0);
    gemm_ctx<<<dim3(B / 128, (DOUT * 3) / 192), 256, C_SMEM, s2>>>(
        xh, whA2, DIN, DOUT, c2, T2);
    gln_rescue<<<(B * DOUT / 4 + 255) / 256, 256, 0, s2>>>(
        c2, x, H2, T2, B * DOUT / 4, DOUT, DIN);
    cudaEventRecord(evC2, s2);

    // ---- s0 (critical path): layer-0 context then the select chain ----
    conv(H0, whA0, (size_t)DLAT * 3 * DIN, s0);
    gemm_ctx<<<dim3(B / 128, (DLAT * 3) / 192), 256, C_SMEM, s0>>>(
        xh, whA0, DIN, DLAT, c0, T0);
    gln_rescue<<<(B * DLAT / 4 + 255) / 256, 256, 0, s0>>>(
        c0, x, H0, T0, B * DLAT / 4, DLAT, DIN);

    cudaStreamWaitEvent(s0, evW0, 0);
    gemm_sel<1><<<dim3(B / 128, (DLAT * 8) / 128), 256, S_SMEM, s0>>>(
        xh, wh0, DIN, DLAT, c0, nullptr, nullptr, hA);

    cudaStreamWaitEvent(s0, evC1, 0);
    cudaStreamWaitEvent(s0, evW1, 0);
    gemm_sel<1><<<dim3(B / 128, (DLAT * 8) / 128), 256, S_SMEM, s0>>>(
        hA, wh1, DLAT, DLAT, c1, b1, nullptr, hB);

    cudaStreamWaitEvent(s0, evC2, 0);
    cudaStreamWaitEvent(s0, evW2, 0);
    gemm_sel<2><<<dim3(B / 128, (DOUT * 8) / 128), 256, S_SMEM, s0>>>(
        hB, wh2, DLAT, DOUT, c2, b2, out, nullptr);

    (void)in_sizes; (void)n_in; (void)out_size;
}

// round 15
// speedup vs baseline: 1.0824x; 1.0056x over previous
#include <cuda_runtime.h>
#include <cuda_fp16.h>
#include <cstdint>
#include <cstddef>
#include <math.h>

// ---------------------------------------------------------------------------
// GLN_56006373539841: HMMA fp16 GEMM, single-pass (R10 kernels, byte-identical).
// R15: conv(H0) moved off the critical path (doesn't need x); side streams
//      created with LOWEST priority so critical-path GEMMs win SM arbitration.
//   B=4096, D_IN=1024, D_LAT=2048, D_OUT=1024, SHATTER=3, NC=8
// ---------------------------------------------------------------------------

#define RESCUE_TAU 0.08f
#define PITCH   80                    // 64B data + 16B pad (KC=32 fp16 rows)

// select GEMM (NT=128): 2 tiles (A, B), 3 stages -> 2 CTAs/SM
#define SSTAGES 3
#define S_TILE  (128 * PITCH)         // 10240
#define S_STAGE (2 * S_TILE)          // 20480
#define S_SMEM  (SSTAGES * S_STAGE)   // 61440

// ctx GEMM (NT=192): 2 tiles (A, B), 4 stages (1 CTA/SM, reg-heavy)
#define CSTAGES 4
#define C_AB    (128 * PITCH)         // 10240
#define C_BB    (192 * PITCH)         // 15360
#define C_STAGE (C_AB + C_BB)         // 25600
#define C_SMEM  (CSTAGES * C_STAGE)   // 102400
#define SC_PITCH 194                  // score staging pitch (floats)

// ============================ PTX helpers ==================================
__device__ __forceinline__ uint32_t smem_u32(const void* p) {
    uint32_t a;
    asm("{ .reg .u64 t; cvta.to.shared.u64 t, %1; cvt.u32.u64 %0, t; }"
        : "=r"(a) : "l"(p));
    return a;
}
__device__ __forceinline__ void cp16(uint32_t dst, const void* src) {
    asm volatile("cp.async.cg.shared.global [%0], [%1], 16;" :: "r"(dst), "l"(src));
}
#define CP_COMMIT() asm volatile("cp.async.commit_group;" ::: "memory")

__device__ __forceinline__ void ldsm4(uint32_t* r, uint32_t addr) {
    asm volatile("ldmatrix.sync.aligned.m8n8.x4.shared.b16 {%0,%1,%2,%3}, [%4];"
        : "=r"(r[0]), "=r"(r[1]), "=r"(r[2]), "=r"(r[3]) : "r"(addr));
}
__device__ __forceinline__ void hmma(float* d, const uint32_t* a, const uint32_t* b) {
    asm volatile("mma.sync.aligned.m16n8k16.row.col.f32.f16.f16.f32 "
        "{%0,%1,%2,%3},{%4,%5,%6,%7},{%8,%9},{%0,%1,%2,%3};"
        : "+f"(d[0]), "+f"(d[1]), "+f"(d[2]), "+f"(d[3])
        : "r"(a[0]), "r"(a[1]), "r"(a[2]), "r"(a[3]), "r"(b[0]), "r"(b[1]));
}

// ============================ scratch ======================================
__device__ __half g_xh  [4096u * 1024u];
__device__ __half g_hA  [4096u * 2048u];
__device__ __half g_hB  [4096u * 2048u];
__device__ __half g_whA0[6144u * 1024u];    // H0 fp16
__device__ __half g_whA1[6144u * 1024u];    // H1 fp16
__device__ __half g_whA2[3072u * 1024u];    // H2 fp16
__device__ __half g_wh0 [16384u * 1024u];   // W0 fp16
__device__ __half g_wh1 [16384u * 2048u];   // W1 fp16
__device__ __half g_wh2 [8192u  * 2048u];   // W2 fp16
__device__ unsigned char g_ctx0[4096u * 2048u];
__device__ unsigned char g_ctx1[4096u * 2048u];
__device__ unsigned char g_ctx2[4096u * 1024u];

// ============================ convert kernel ===============================
__global__ void conv_hi(const float* __restrict__ in, __half* __restrict__ hi, int n4)
{
    int i = blockIdx.x * blockDim.x + threadIdx.x;
    if (i >= n4) return;
    float4 v = ((const float4*)in)[i];
    ((__half2*)hi)[i * 2 + 0] = __halves2half2(__float2half_rn(v.x), __float2half_rn(v.y));
    ((__half2*)hi)[i * 2 + 1] = __halves2half2(__float2half_rn(v.z), __float2half_rn(v.w));
}

// ============================ ctx GEMM (fused combine) =====================
// CTA 128M x 192N, 8 warps (4M x 2N), warp tile 32x96.  (R10, byte-identical)
// Output byte: bits 0-2 ctx index, bits 3-5 per-score rescue flags.
__global__ __launch_bounds__(256, 1)
void gemm_ctx(const __half* __restrict__ Ahi, const __half* __restrict__ Bhi,
              int K, int O,
              unsigned char* __restrict__ ctxout, const float* __restrict__ T)
{
    extern __shared__ char smraw[];
    const uint32_t smb = smem_u32(smraw);
    const int tid  = threadIdx.x;
    const int lane = tid & 31;
    const int wid  = tid >> 5;
    const int wm   = wid & 3;
    const int wn   = wid >> 2;
    const int row0 = blockIdx.x * 128;
    const int col0 = blockIdx.y * 192;

    const __half* gA = Ahi + (size_t)row0 * K;
    const __half* gB = Bhi + (size_t)col0 * K;

    float acc[2][12][4];
#pragma unroll
    for (int i = 0; i < 2; i++)
#pragma unroll
        for (int j = 0; j < 12; j++)
#pragma unroll
            for (int q = 0; q < 4; q++) acc[i][j][q] = 0.0f;

    const int nk = K >> 5;

    auto issue = [&](int s) {
        uint32_t base = smb + (uint32_t)(s & (CSTAGES - 1)) * C_STAGE;
        int k0 = s * 32;
#pragma unroll
        for (int t = 0; t < 2; t++) {           // A: 512 cp16
            int id = tid + t * 256;
            int r  = id >> 2, c = id & 3;
            cp16(base + r * PITCH + c * 16, gA + (size_t)r * K + k0 + c * 8);
        }
#pragma unroll
        for (int t = 0; t < 3; t++) {           // B: 768 cp16
            int id = tid + t * 256;
            int r  = id >> 2, c = id & 3;
            cp16(base + C_AB + r * PITCH + c * 16, gB + (size_t)r * K + k0 + c * 8);
        }
        CP_COMMIT();
    };

#pragma unroll
    for (int s = 0; s < CSTAGES - 1; s++) issue(s);

    const uint32_t lrow = (uint32_t)(lane & 15);
    const uint32_t lhal = (uint32_t)(lane >> 4) * 16;

    for (int it = 0; it < nk; it++) {
        asm volatile("cp.async.wait_group 2;" ::: "memory");
        __syncthreads();
        int pf = it + CSTAGES - 1;
        if (pf < nk) issue(pf); else CP_COMMIT();

        uint32_t stg = smb + (uint32_t)(it & (CSTAGES - 1)) * C_STAGE;
#pragma unroll
        for (int k16 = 0; k16 < 2; k16++) {
            uint32_t koff = lhal + (uint32_t)k16 * 32;
            uint32_t ah[2][4];
#pragma unroll
            for (int mi = 0; mi < 2; mi++) {
                uint32_t ro = (uint32_t)(wm * 32 + mi * 16) + lrow;
                ldsm4(ah[mi], stg + ro * PITCH + koff);
            }
            uint32_t bh[12][2];
#pragma unroll
            for (int jj = 0; jj < 6; jj++) {
                uint32_t ro = (uint32_t)(wn * 96 + jj * 16) + lrow;
                uint32_t r4[4];
                ldsm4(r4, stg + C_AB + ro * PITCH + koff);
                bh[jj * 2][0] = r4[0]; bh[jj * 2][1] = r4[2];
                bh[jj * 2 + 1][0] = r4[1]; bh[jj * 2 + 1][1] = r4[3];
            }
#pragma unroll
            for (int mi = 0; mi < 2; mi++)
#pragma unroll
                for (int nj = 0; nj < 12; nj++) hmma(acc[mi][nj], ah[mi], bh[nj]);
        }
    }
    asm volatile("cp.async.wait_group 0;" ::: "memory");
    __syncthreads();

    // ---- stage scores into smem ----
    float* ssc = (float*)smraw;
    const int rr = lane >> 2;
    const int q2 = (lane & 3) * 2;
#pragma unroll
    for (int mi = 0; mi < 2; mi++) {
        int r_lo = wm * 32 + mi * 16 + rr;
        int r_hi = r_lo + 8;
#pragma unroll
        for (int nj = 0; nj < 12; nj++) {
            int c = wn * 96 + nj * 8 + q2;
            *(float2*)&ssc[r_lo * SC_PITCH + c] = make_float2(acc[mi][nj][0], acc[mi][nj][1]);
            *(float2*)&ssc[r_hi * SC_PITCH + c] = make_float2(acc[mi][nj][2], acc[mi][nj][3]);
        }
    }
    __syncthreads();

    // ---- combine: 128 rows x 64 o-groups -> 2048 uint32 words ----
    const int oc0 = col0 / 3;
#pragma unroll
    for (int w8 = 0; w8 < 8; w8++) {
        int word_id = tid + w8 * 256;
        int r  = word_id >> 4;
        int wo = word_id & 15;
        const float* sp = ssc + r * SC_PITCH + wo * 12;
        uint32_t word = 0;
#pragma unroll
        for (int j = 0; j < 4; j++) {
            int o = oc0 + wo * 4 + j;
            int c = 0;
#pragma unroll
            for (int s = 0; s < 3; s++) {
                float th = __ldg(T + o * 3 + s);
                float d  = sp[j * 3 + s] - th;
                c |= ((int)(d > 0.0f)) << s;
                c |= ((int)(fabsf(d) < RESCUE_TAU)) << (3 + s);
            }
            word |= (uint32_t)((unsigned char)c) << (j * 8);
        }
        *(uint32_t*)(ctxout + (size_t)(row0 + r) * O + oc0 + wo * 4) = word;
    }
}

// ============================ warp-cooperative fp64 rescue =================
__global__ void gln_rescue(unsigned char* __restrict__ ctx,
                           const float* __restrict__ z,
                           const float* __restrict__ H,
                           const float* __restrict__ T,
                           int total4, int O, int K)
{
    int i    = blockIdx.x * blockDim.x + threadIdx.x;
    int lane = threadIdx.x & 31;
    uint32_t w = (i < total4) ? ((const uint32_t*)ctx)[i] : 0u;
    unsigned m = __ballot_sync(0xFFFFFFFFu, (w & 0x38383838u) != 0u);
    while (m) {
        int src = __ffs(m) - 1; m &= m - 1;
        uint32_t sw = __shfl_sync(0xFFFFFFFFu, w, src);
        int si = __shfl_sync(0xFFFFFFFFu, i, src);
#pragma unroll
        for (int j = 0; j < 4; j++) {
            uint32_t byte = (sw >> (j * 8)) & 0xFF;
            if (!(byte & 0x38)) continue;
            int idx = si * 4 + j;
            int b = idx / O, o = idx - b * O;
            const float* zr = z + (size_t)b * K;
            int c = (int)(byte & 7);
#pragma unroll
            for (int s = 0; s < 3; s++) {
                if (!(byte & (8u << s))) continue;
                const float* hr = H + (size_t)(o * 3 + s) * K;
                double p0 = 0.0, p1 = 0.0;
                for (int k = lane; k < K; k += 64) {
                    p0 += (double)zr[k]      * (double)hr[k];
                    p1 += (double)zr[k + 32] * (double)hr[k + 32];
                }
                double part = p0 + p1;
#pragma unroll
                for (int off = 16; off; off >>= 1)
                    part += __shfl_down_sync(0xFFFFFFFFu, part, off);
                part = __shfl_sync(0xFFFFFFFFu, part, 0);
                c = (c & ~(1 << s)) | (((int)(part > (double)T[o * 3 + s])) << s);
            }
            if (lane == 0) ctx[idx] = (unsigned char)c;
        }
    }
}

// ============================ select GEMM ==================================
// CTA 128x128, 8 warps (4M x 2N), warp tile 32x64.  3-stage smem + 2 CTAs/SM.
// MODE 1: hidden -> fp16.  MODE 2: final -> fp32.  (R10, byte-identical)
template <int MODE>
__global__ __launch_bounds__(256, 2)
void gemm_sel(const __half* __restrict__ Ahi, const __half* __restrict__ Bhi,
              int K, int O,
              const unsigned char* __restrict__ ctx, const float* __restrict__ bias,
              float* __restrict__ outf, __half* __restrict__ outh)
{
    extern __shared__ char smraw[];
    const uint32_t smb = smem_u32(smraw);
    const int tid  = threadIdx.x;
    const int lane = tid & 31;
    const int wid  = tid >> 5;
    const int wm   = wid & 3;
    const int wn   = wid >> 2;
    const int row0 = blockIdx.x * 128;
    const int col0 = blockIdx.y * 128;

    const __half* gA = Ahi + (size_t)row0 * K;
    const __half* gB = Bhi + (size_t)col0 * K;

    float acc[2][8][4];
#pragma unroll
    for (int i = 0; i < 2; i++)
#pragma unroll
        for (int j = 0; j < 8; j++)
#pragma unroll
            for (int q = 0; q < 4; q++) acc[i][j][q] = 0.0f;

    const int nk = K >> 5;

    auto issue = [&](int s) {
        uint32_t base = smb + (uint32_t)((unsigned)s % 3u) * S_STAGE;
        int k0 = s * 32;
#pragma unroll
        for (int t = 0; t < 4; t++) {           // 1024 cp16
            int id   = tid + t * 256;
            int tile = id >> 9;                 // 0..1
            int r    = (id >> 2) & 127;
            int c    = id & 3;
            const __half* g = tile ? gB : gA;
            cp16(base + tile * S_TILE + r * PITCH + c * 16,
                 g + (size_t)r * K + k0 + c * 8);
        }
        CP_COMMIT();
    };

#pragma unroll
    for (int s = 0; s < SSTAGES - 1; s++) issue(s);   // 2 groups in flight

    const uint32_t lrow = (uint32_t)(lane & 15);
    const uint32_t lhal = (uint32_t)(lane >> 4) * 16;

    for (int it = 0; it < nk; it++) {
        asm volatile("cp.async.wait_group 1;" ::: "memory");   // oldest done
        __syncthreads();
        int pf = it + SSTAGES - 1;
        if (pf < nk) issue(pf); else CP_COMMIT();

        uint32_t stg = smb + (uint32_t)((unsigned)it % 3u) * S_STAGE;
#pragma unroll
        for (int k16 = 0; k16 < 2; k16++) {
            uint32_t koff = lhal + (uint32_t)k16 * 32;
            uint32_t ah[2][4];
#pragma unroll
            for (int mi = 0; mi < 2; mi++) {
                uint32_t ro = (uint32_t)(wm * 32 + mi * 16) + lrow;
                ldsm4(ah[mi], stg + ro * PITCH + koff);
            }
            uint32_t bh[8][2];
#pragma unroll
            for (int jj = 0; jj < 4; jj++) {
                uint32_t ro = (uint32_t)(wn * 64 + jj * 16) + lrow;
                uint32_t r4[4];
                ldsm4(r4, stg + S_TILE + ro * PITCH + koff);
                bh[jj * 2][0] = r4[0]; bh[jj * 2][1] = r4[2];
                bh[jj * 2 + 1][0] = r4[1]; bh[jj * 2 + 1][1] = r4[3];
            }
#pragma unroll
            for (int mi = 0; mi < 2; mi++)
#pragma unroll
                for (int nj = 0; nj < 8; nj++) hmma(acc[mi][nj], ah[mi], bh[nj]);
        }
    }

    // ---- 1-of-8 select epilogue ----
    const int rr = lane >> 2;
    const int q2 = (lane & 3) * 2;
#pragma unroll
    for (int mi = 0; mi < 2; mi++) {
        int r_lo = row0 + wm * 32 + mi * 16 + rr;
        int r_hi = r_lo + 8;
#pragma unroll
        for (int nj = 0; nj < 8; nj++) {
            int o   = (col0 + wn * 64 + nj * 8) >> 3;
            int cb0 = ctx[(size_t)r_lo * O + o] & 7;
            int cb1 = ctx[(size_t)r_hi * O + o] & 7;
            if (cb0 == q2 || cb0 == q2 + 1) {
                float v = (cb0 == q2) ? acc[mi][nj][0] : acc[mi][nj][1];
                if (bias) v += bias[o * 8 + cb0];
                size_t idx = (size_t)r_lo * O + o;
                if (MODE == 1) outh[idx] = __float2half_rn(v);
                else           outf[idx] = v;
            }
            if (cb1 == q2 || cb1 == q2 + 1) {
                float v = (cb1 == q2) ? acc[mi][nj][2] : acc[mi][nj][3];
                if (bias) v += bias[o * 8 + cb1];
                size_t idx = (size_t)r_hi * O + o;
                if (MODE == 1) outh[idx] = __float2half_rn(v);
                else           outf[idx] = v;
            }
        }
    }
}

// ============================ host =========================================
extern "C" void kernel_launch(void* const* d_in, const int* in_sizes, int n_in,
                              void* d_out, int out_size)
{
    const float* x  = (const float*)d_in[0];
    const float* W0 = (const float*)d_in[1];
    const float* W1 = (const float*)d_in[2];
    const float* W2 = (const float*)d_in[3];
    const float* b1 = (const float*)d_in[4];
    const float* b2 = (const float*)d_in[5];
    const float* H0 = (const float*)d_in[6];
    const float* T0 = (const float*)d_in[7];
    const float* H1 = (const float*)d_in[8];
    const float* T1 = (const float*)d_in[9];
    const float* H2 = (const float*)d_in[10];
    const float* T2 = (const float*)d_in[11];
    float* out = (float*)d_out;

    void *p;
    cudaGetSymbolAddress(&p, g_xh);   __half* xh   = (__half*)p;
    cudaGetSymbolAddress(&p, g_hA);   __half* hA   = (__half*)p;
    cudaGetSymbolAddress(&p, g_hB);   __half* hB   = (__half*)p;
    cudaGetSymbolAddress(&p, g_whA0); __half* whA0 = (__half*)p;
    cudaGetSymbolAddress(&p, g_whA1); __half* whA1 = (__half*)p;
    cudaGetSymbolAddress(&p, g_whA2); __half* whA2 = (__half*)p;
    cudaGetSymbolAddress(&p, g_wh0);  __half* wh0  = (__half*)p;
    cudaGetSymbolAddress(&p, g_wh1);  __half* wh1  = (__half*)p;
    cudaGetSymbolAddress(&p, g_wh2);  __half* wh2  = (__half*)p;
    cudaGetSymbolAddress(&p, g_ctx0); unsigned char* c0 = (unsigned char*)p;
    cudaGetSymbolAddress(&p, g_ctx1); unsigned char* c1 = (unsigned char*)p;
    cudaGetSymbolAddress(&p, g_ctx2); unsigned char* c2 = (unsigned char*)p;

    const int B = 4096, DIN = 1024, DLAT = 2048, DOUT = 1024;

    // One-time resources (created on the first, uncaptured, correctness call).
    static cudaStream_t s1 = nullptr, s2 = nullptr, s3 = nullptr;
    static cudaEvent_t evFork, evX, evH0, evC1, evC2, evW0, evW1, evW2;
    static bool inited = false;
    if (!inited) {
        int prLeast = 0, prGreatest = 0;
        cudaDeviceGetStreamPriorityRange(&prLeast, &prGreatest);
        // prLeast = lowest priority. Side streams yield to the critical path.
        cudaStreamCreateWithPriority(&s1, cudaStreamNonBlocking, prLeast);
        cudaStreamCreateWithPriority(&s2, cudaStreamNonBlocking, prLeast);
        cudaStreamCreateWithPriority(&s3, cudaStreamNonBlocking, prLeast);
        cudaEventCreateWithFlags(&evFork, cudaEventDisableTiming);
        cudaEventCreateWithFlags(&evX,    cudaEventDisableTiming);
        cudaEventCreateWithFlags(&evH0,   cudaEventDisableTiming);
        cudaEventCreateWithFlags(&evC1,   cudaEventDisableTiming);
        cudaEventCreateWithFlags(&evC2,   cudaEventDisableTiming);
        cudaEventCreateWithFlags(&evW0,   cudaEventDisableTiming);
        cudaEventCreateWithFlags(&evW1,   cudaEventDisableTiming);
        cudaEventCreateWithFlags(&evW2,   cudaEventDisableTiming);
        cudaFuncSetAttribute(gemm_ctx,    cudaFuncAttributeMaxDynamicSharedMemorySize, C_SMEM);
        cudaFuncSetAttribute(gemm_sel<1>, cudaFuncAttributeMaxDynamicSharedMemorySize, S_SMEM);
        cudaFuncSetAttribute(gemm_sel<2>, cudaFuncAttributeMaxDynamicSharedMemorySize, S_SMEM);
        inited = true;
    }

    auto conv = [](const float* in, __half* dst, size_t n, cudaStream_t st) {
        int n4 = (int)(n / 4);
        conv_hi<<<(n4 + 255) / 256, 256, 0, st>>>(in, dst, n4);
    };

    cudaStream_t s0 = 0;   // default (capture) stream

    // ---- fork: all side streams join capture BEFORE any of their work ----
    cudaEventRecord(evFork, s0);
    cudaStreamWaitEvent(s1, evFork, 0);
    cudaStreamWaitEvent(s2, evFork, 0);
    cudaStreamWaitEvent(s3, evFork, 0);

    // ---- s0: input convert (only x-dependent op before ctx0) ----
    conv(x, xh, (size_t)B * DIN, s0);
    cudaEventRecord(evX, s0);

    // ---- s3: H0 first (unblocks ctx0), then all weight converts ----
    conv(H0, whA0, (size_t)DLAT * 3 * DIN, s3);
    cudaEventRecord(evH0, s3);
    conv(W0, wh0, (size_t)DLAT * 8 * DIN, s3);
    cudaEventRecord(evW0, s3);
    conv(W1, wh1, (size_t)DLAT * 8 * DLAT, s3);
    cudaEventRecord(evW1, s3);
    conv(W2, wh2, (size_t)DOUT * 8 * DLAT, s3);
    cudaEventRecord(evW2, s3);

    // ---- s1: layer-1 context branch ----
    conv(H1, whA1, (size_t)DLAT * 3 * DIN, s1);
    cudaStreamWaitEvent(s1, evX, 0);
    gemm_ctx<<<dim3(B / 128, (DLAT * 3) / 192), 256, C_SMEM, s1>>>(
        xh, whA1, DIN, DLAT, c1, T1);
    gln_rescue<<<(B * DLAT / 4 + 255) / 256, 256, 0, s1>>>(
        c1, x, H1, T1, B * DLAT / 4, DLAT, DIN);
    cudaEventRecord(evC1, s1);

    // ---- s2: layer-2 context branch ----
    conv(H2, whA2, (size_t)DOUT * 3 * DIN, s2);
    cudaStreamWaitEvent(s2, evX, 0);
    gemm_ctx<<<dim3(B / 128, (DOUT * 3) / 192), 256, C_SMEM, s2>>>(
        xh, whA2, DIN, DOUT, c2, T2);
    gln_rescue<<<(B * DOUT / 4 + 255) / 256, 256, 0, s2>>>(
        c2, x, H2, T2, B * DOUT / 4, DOUT, DIN);
    cudaEventRecord(evC2, s2);

    // ---- s0 (critical path): ctx0 then the select chain ----
    cudaStreamWaitEvent(s0, evH0, 0);
    gemm_ctx<<<dim3(B / 128, (DLAT * 3) / 192), 256, C_SMEM, s0>>>(
        xh, whA0, DIN, DLAT, c0, T0);
    gln_rescue<<<(B * DLAT / 4 + 255) / 256, 256, 0, s0>>>(
        c0, x, H0, T0, B * DLAT / 4, DLAT, DIN);

    cudaStreamWaitEvent(s0, evW0, 0);
    gemm_sel<1><<<dim3(B / 128, (DLAT * 8) / 128), 256, S_SMEM, s0>>>(
        xh, wh0, DIN, DLAT, c0, nullptr, nullptr, hA);

    cudaStreamWaitEvent(s0, evC1, 0);
    cudaStreamWaitEvent(s0, evW1, 0);
    gemm_sel<1><<<dim3(B / 128, (DLAT * 8) / 128), 256, S_SMEM, s0>>>(
        hA, wh1, DLAT, DLAT, c1, b1, nullptr, hB);

    cudaStreamWaitEvent(s0, evC2, 0);
    cudaStreamWaitEvent(s0, evW2, 0);
    gemm_sel<2><<<dim3(B / 128, (DOUT * 8) / 128), 256, S_SMEM, s0>>>(
        hB, wh2, DLAT, DOUT, c2, b2, out, nullptr);

    (void)in_sizes; (void)n_in; (void)out_size;
}